// round 16
// baseline (speedup 1.0000x reference)
#include <cuda_runtime.h>
#include <cuda_bf16.h>

// Shapes (fixed): B=2, N=2048, K=48, A=4
// X: (B,N,4,3) f32; edge_idx: (B,N,48) i32; C: (B,N) i32
// out: (B,N,48,192) f32
//
// R = Q*diag(s): Q orthonormal, s_y=||n_y||. Atoms rotated once by Q^T and
// PRE-MASKED (coords *= mk in {0,1} -> masked diff gives exactly 0 output).
// Per pair: diff + rsqrt + per-axis s_y.
//
// Phase 3: lane owns 4 consecutive pairs = 12 floats = 3 float4s (static
// packing). The lane's 4 b-atoms are 12 CONTIGUOUS floats (48B, 16B-aligned)
// -> loaded with 3 LDS.128 (64B distinct per warp-instr: 1 phase each)
// instead of 12 scalar LDS. Warp covers 2 k-rows per pass; per-warp scratch
// (conflict-free) then coalesced LDS.128 + STG.128; __syncwarp only.

#define BB 2
#define NN 2048
#define KK 48
#define EPS 0.1f
#define THREADS 384
#define ROWF 24

__global__ __launch_bounds__(THREADS) void edge_orient_v16_kernel(
    const float* __restrict__ X,
    const int*   __restrict__ E,
    const int*   __restrict__ C,
    float*       __restrict__ out)
{
    const int bn   = blockIdx.x;
    const int b    = bn >> 11;        // / NN
    const int t    = threadIdx.x;
    const int w    = t >> 5;
    const int lane = t & 31;

    __shared__ __align__(16) float  sA[KK * ROWF];   // rotated+masked coords
    __shared__ __align__(16) float4 sScr[12][96];    // per-warp scratch
    __shared__ int   sJ[KK];
    __shared__ float sR[9];
    __shared__ float sS[3];

    const int* e_row = E + (size_t)bn * KK;

    // ---- phase 1: raw coords + neighbor idx + frame ----
    if (t < KK) sJ[t] = e_row[t];
    if (t < KK * 6) {
        const int k  = t / 6;
        const int qq = t - k * 6;
        if (qq < 3) {
            ((float4*)&sA[k * ROWF])[qq] = ((const float4*)(X + (size_t)bn * 12))[qq];
        } else {
            const int j = e_row[k];
            ((float4*)&sA[k * ROWF])[qq] =
                ((const float4*)(X + ((size_t)(b * NN + j)) * 12))[qq - 3];
        }
    }
    if (t == 336) {
        const float* xr = X + (size_t)bn * 12;
        float Nx = xr[0], Ny = xr[1], Nz = xr[2];
        float Ax = xr[3], Ay = xr[4], Az = xr[5];
        float Cx = xr[6], Cy = xr[7], Cz = xr[8];

        float ux = Nx - Ax, uy = Ny - Ay, uz = Nz - Az;
        float invE = rsqrtf(ux*ux + uy*uy + uz*uz + EPS);
        float n1x = ux*invE, n1y = uy*invE, n1z = uz*invE;
        float n1n2 = n1x*n1x + n1y*n1y + n1z*n1z;
        float inv0 = rsqrtf(n1n2);
        float q1x = n1x*inv0, q1y = n1y*inv0, q1z = n1z*inv0;
        float s1  = n1n2 * inv0;

        float vx = Cx - Ax, vy = Cy - Ay, vz = Cz - Az;
        float invV = rsqrtf(vx*vx + vy*vy + vz*vz + EPS);
        vx *= invV; vy *= invV; vz *= invV;

        float c2x = n1y*vz - n1z*vy;
        float c2y = n1z*vx - n1x*vz;
        float c2z = n1x*vy - n1y*vx;
        invE = rsqrtf(c2x*c2x + c2y*c2y + c2z*c2z + EPS);
        float n2x = c2x*invE, n2y = c2y*invE, n2z = c2z*invE;
        float n2n2 = n2x*n2x + n2y*n2y + n2z*n2z;
        inv0 = rsqrtf(n2n2);
        float q2x = n2x*inv0, q2y = n2y*inv0, q2z = n2z*inv0;
        float s2  = n2n2 * inv0;

        float c3x = n1y*n2z - n1z*n2y;
        float c3y = n1z*n2x - n1x*n2z;
        float c3z = n1x*n2y - n1y*n2x;
        invE = rsqrtf(c3x*c3x + c3y*c3y + c3z*c3z + EPS);
        float n3x = c3x*invE, n3y = c3y*invE, n3z = c3z*invE;
        float n3n2 = n3x*n3x + n3y*n3y + n3z*n3z;
        inv0 = rsqrtf(n3n2);

        sR[0] = q1x;      sR[1] = q1y;      sR[2] = q1z;
        sR[3] = q2x;      sR[4] = q2y;      sR[5] = q2z;
        sR[6] = n3x*inv0; sR[7] = n3y*inv0; sR[8] = n3z*inv0;
        sS[0] = s1; sS[1] = s2; sS[2] = n3n2 * inv0;
    }
    __syncthreads();

    // ---- phase 2: rotate + mask all atoms in place ----
    {
        const int k = t >> 3;
        const int a = (t & 7) * 3;
        const int j = sJ[k];
        const float mk = ((C[bn] > 0) && (C[b * NN + j] > 0)) ? 1.0f : 0.0f;
        float* p = &sA[k * ROWF + a];
        const float x = p[0], y = p[1], z = p[2];
        const float rx = (x*sR[0] + y*sR[1] + z*sR[2]) * mk;
        const float ry = (x*sR[3] + y*sR[4] + z*sR[5]) * mk;
        const float rz = (x*sR[6] + y*sR[7] + z*sR[8]) * mk;
        __syncthreads();
        p[0] = rx; p[1] = ry; p[2] = rz;
    }
    __syncthreads();

    const float s1 = sS[0], s2 = sS[1], s3 = sS[2];

    // ---- phase 3: lane = 4 pairs; b-atoms loaded as 3 x LDS.128 ----
    const int rowsel = lane >> 4;
    const int aIdx   = (lane & 15) >> 1;
    const int bBase  = (lane & 1) * 4;

    float4* scr = &sScr[w][0];
    float4* obase = (float4*)(out + (size_t)bn * (KK * 192));

#pragma unroll
    for (int pass = 0; pass < 2; pass++) {
        const int rp  = w + 12 * pass;        // row-pair 0..23
        const int row = 2 * rp + rowsel;      // this lane's k row

        const float* rbase = &sA[row * ROWF];
        const float ax = rbase[3 * aIdx + 0];
        const float ay = rbase[3 * aIdx + 1];
        const float az = rbase[3 * aIdx + 2];

        // 4 b-atoms = 12 contiguous floats at rbase + 3*bBase (16B aligned)
        const float4* rb4 = (const float4*)(rbase + 3 * bBase);
        const float4 g0 = rb4[0];
        const float4 g1 = rb4[1];
        const float4 g2 = rb4[2];
        const float f0 = g0.x, f1 = g0.y, f2  = g0.z, f3  = g0.w;
        const float f4 = g1.x, f5 = g1.y, f6  = g1.z, f7  = g1.w;
        const float f8 = g2.x, f9 = g2.y, f10 = g2.z, f11 = g2.w;

        float v[12];
        {
            const float dx = f0 - ax, dy = f1 - ay, dz = f2 - az;
            float nn = fmaf(dx, dx, EPS); nn = fmaf(dy, dy, nn); nn = fmaf(dz, dz, nn);
            const float inv = rsqrtf(nn);
            v[0] = dx * inv * s1; v[1] = dy * inv * s2; v[2] = dz * inv * s3;
        }
        {
            const float dx = f3 - ax, dy = f4 - ay, dz = f5 - az;
            float nn = fmaf(dx, dx, EPS); nn = fmaf(dy, dy, nn); nn = fmaf(dz, dz, nn);
            const float inv = rsqrtf(nn);
            v[3] = dx * inv * s1; v[4] = dy * inv * s2; v[5] = dz * inv * s3;
        }
        {
            const float dx = f6 - ax, dy = f7 - ay, dz = f8 - az;
            float nn = fmaf(dx, dx, EPS); nn = fmaf(dy, dy, nn); nn = fmaf(dz, dz, nn);
            const float inv = rsqrtf(nn);
            v[6] = dx * inv * s1; v[7] = dy * inv * s2; v[8] = dz * inv * s3;
        }
        {
            const float dx = f9 - ax, dy = f10 - ay, dz = f11 - az;
            float nn = fmaf(dx, dx, EPS); nn = fmaf(dy, dy, nn); nn = fmaf(dz, dz, nn);
            const float inv = rsqrtf(nn);
            v[9] = dx * inv * s1; v[10] = dy * inv * s2; v[11] = dz * inv * s3;
        }

        scr[3*lane + 0] = make_float4(v[0], v[1], v[2],  v[3]);
        scr[3*lane + 1] = make_float4(v[4], v[5], v[6],  v[7]);
        scr[3*lane + 2] = make_float4(v[8], v[9], v[10], v[11]);

        __syncwarp();

        float4* od = obase + rp * 96;
#pragma unroll
        for (int i = 0; i < 3; i++) {
            od[32*i + lane] = scr[32*i + lane];
        }

        __syncwarp();
    }
}

extern "C" void kernel_launch(void* const* d_in, const int* in_sizes, int n_in,
                              void* d_out, int out_size) {
    const float* X = (const float*)d_in[0];
    const int*   E = (const int*)d_in[1];
    const int*   C = (const int*)d_in[2];
    float* out = (float*)d_out;

    edge_orient_v16_kernel<<<BB * NN, THREADS>>>(X, E, C, out);
}